// round 7
// baseline (speedup 1.0000x reference)
#include <cuda_runtime.h>
#include <cuda_fp16.h>
#include <cstdint>
#include <cstddef>

// ---------------------------------------------------------------------------
// TicRows via mma.sync m16n8k16 (fp16 in, fp32 acc).
// R7: 64x64 warp tiles (4:1 MMA:ldmatrix), BN=256 (full row block per CTA),
// 3-stage cp.async pipeline with ONE __syncthreads per k-chunk.
// Pre-pass: x -> fp16 g_xh (same layout), v -> fp16 g_vT[r][n][k] k-contiguous.
// out[n, r*256+c] = sum_{e,i} x[n, cell[r][e]*64+i]*v[e,i,r,c] + b[r*256+c]
// ---------------------------------------------------------------------------

#define BATCH   8192
#define ROWS    49
#define CH      256
#define XCOLS   1728
#define OUTCOLS 12544
#define KDIM    192
#define BM      128
#define BN      256
#define NCHUNK  6
#define THREADS 256
#define SSTR    40            // smem row stride in halves: conflict-free ldmatrix
#define ABUF    (BM * SSTR)   // 5120 halves
#define BBUF    (BN * SSTR)   // 10240 halves

__device__ int    d_cell[ROWS * 3];
__device__ __half g_xh[(size_t)BATCH * XCOLS];          // 28.3 MB
__device__ __half g_vT[(size_t)ROWS * CH * KDIM];       // 4.8 MB, [r][n][k]

__global__ void init_cells_kernel() {
    if (threadIdx.x != 0) return;
    int step = 0, col = 0;
    auto put = [&](int x, int y, int z) {
        d_cell[col * 3 + step] = x + 3 * y + 9 * z;
        step = (step + 1) % 3;
    };
    for (int x = 0; x < 3; x++) {
        for (int y = 0; y < 3; y++) { for (int z = 0; z < 3; z++) put(x, y, z); col++; }
        for (int z = 0; z < 3; z++) { for (int y = 0; y < 3; y++) put(x, y, z); col++; }
        for (int y = 0; y < 3; y++) put(x, y, y);       col++;
        for (int y = 0; y < 3; y++) put(x, y, 2 - y);   col++;
    }
    for (int z = 0; z < 3; z++) {
        for (int y = 0; y < 3; y++) { for (int x = 0; x < 3; x++) put(x, y, z); col++; }
        for (int y = 0; y < 3; y++) put(y, y, z);       col++;
        for (int y = 0; y < 3; y++) put(2 - y, y, z);   col++;
    }
    for (int y = 0; y < 3; y++) {
        for (int z = 0; z < 3; z++) put(z, y, z);       col++;
        for (int z = 0; z < 3; z++) put(2 - z, y, z);   col++;
    }
    for (int x = 0; x < 3; x++) put(x, x, x);           col++;
    for (int x = 0; x < 3; x++) put(x, 2 - x, 2 - x);   col++;
    for (int x = 0; x < 3; x++) put(x, x, 2 - x);       col++;
    for (int x = 0; x < 3; x++) put(x, 2 - x, x);       col++;
}

__global__ void convert_x_kernel(const float* __restrict__ x) {
    const size_t i8 = ((size_t)blockIdx.x * blockDim.x + threadIdx.x) * 8;
    float4 a = *(const float4*)(x + i8);
    float4 b = *(const float4*)(x + i8 + 4);
    __half2 h[4] = { __floats2half2_rn(a.x, a.y), __floats2half2_rn(a.z, a.w),
                     __floats2half2_rn(b.x, b.y), __floats2half2_rn(b.z, b.w) };
    *(uint4*)(g_xh + i8) = *(uint4*)h;
}

__global__ void convert_v_kernel(const float* __restrict__ v) {
    const int r = blockIdx.x, n = threadIdx.x;
    const float* src = v + (size_t)r * CH + n;
    __half* dst = g_vT + ((size_t)r * CH + n) * KDIM;
#pragma unroll 1
    for (int kg = 0; kg < KDIM / 8; kg++) {
        __half2 h[4];
#pragma unroll
        for (int j = 0; j < 4; j++) {
            float f0 = src[(size_t)(kg * 8 + 2 * j)     * OUTCOLS];
            float f1 = src[(size_t)(kg * 8 + 2 * j + 1) * OUTCOLS];
            h[j] = __floats2half2_rn(f0, f1);
        }
        *(uint4*)(dst + kg * 8) = *(uint4*)h;
    }
}

// ------------------------------ PTX helpers -------------------------------

__device__ __forceinline__ uint32_t smem_u32(const void* p) {
    uint32_t a;
    asm("{ .reg .u64 t; cvta.to.shared.u64 t, %1; cvt.u32.u64 %0, t; }"
        : "=r"(a) : "l"(p));
    return a;
}

__device__ __forceinline__ void cp16(uint32_t dst, const void* src) {
    asm volatile("cp.async.ca.shared.global [%0], [%1], 16;"
                 :: "r"(dst), "l"(src) : "memory");
}
#define CP_COMMIT()  asm volatile("cp.async.commit_group;" ::: "memory")
#define CP_WAIT(n)   asm volatile("cp.async.wait_group %0;" :: "n"(n) : "memory")

__device__ __forceinline__ void ldmx4(uint32_t* r, uint32_t addr) {
    asm volatile("ldmatrix.sync.aligned.m8n8.x4.shared.b16 {%0,%1,%2,%3}, [%4];"
                 : "=r"(r[0]), "=r"(r[1]), "=r"(r[2]), "=r"(r[3]) : "r"(addr));
}

__device__ __forceinline__ void mma16816(float* c, uint32_t a0, uint32_t a1,
                                         uint32_t a2, uint32_t a3,
                                         uint32_t b0, uint32_t b1) {
    asm volatile(
        "mma.sync.aligned.m16n8k16.row.col.f32.f16.f16.f32 "
        "{%0,%1,%2,%3}, {%4,%5,%6,%7}, {%8,%9}, {%0,%1,%2,%3};"
        : "+f"(c[0]), "+f"(c[1]), "+f"(c[2]), "+f"(c[3])
        : "r"(a0), "r"(a1), "r"(a2), "r"(a3), "r"(b0), "r"(b1));
}

// ------------------------------- main kernel ------------------------------

__global__ __launch_bounds__(THREADS, 1)
void ticrows_hmma(const float* __restrict__ bias, float* __restrict__ out) {
    __shared__ __half sA[3][ABUF];
    __shared__ __half sB[3][BBUF];

    const int tid  = threadIdx.x;
    const int lane = tid & 31;
    const int wid  = tid >> 5;
    const int wm   = wid & 1;            // 2 warps along M -> 64 rows each
    const int wn   = wid >> 1;           // 4 warps along N -> 64 cols each
    const int m0   = blockIdx.x * BM;
    const int r    = blockIdx.y;

    const int ce0 = d_cell[r * 3 + 0];
    const int ce1 = d_cell[r * 3 + 1];
    const int ce2 = d_cell[r * 3 + 2];

    const uint32_t sa_base = smem_u32(sA);
    const uint32_t sb_base = smem_u32(sB);

    // staging: A = 128 rows x 32 k -> 512 cp16 (2/thread);
    //          B = 256 n    x 32 k -> 1024 cp16 (4/thread)
    auto stage = [&](int kc, int buf) {
        const int e       = kc >> 1;
        const int colbase = (e == 0 ? ce0 : (e == 1 ? ce1 : ce2)) * 64 + (kc & 1) * 32;
        const __half* xb  = g_xh + (size_t)m0 * XCOLS + colbase;
        const __half* vb  = g_vT + (size_t)r * CH * KDIM + kc * 32;
        const uint32_t da = sa_base + buf * (ABUF * 2);
        const uint32_t db = sb_base + buf * (BBUF * 2);
#pragma unroll
        for (int i = 0; i < 2; i++) {
            const int c = tid + i * 256, row = c >> 2, seg = c & 3;
            cp16(da + (row * SSTR + seg * 8) * 2, xb + (size_t)row * XCOLS + seg * 8);
        }
#pragma unroll
        for (int i = 0; i < 4; i++) {
            const int c = tid + i * 256, row = c >> 2, seg = c & 3;
            cp16(db + (row * SSTR + seg * 8) * 2, vb + (size_t)row * KDIM + seg * 8);
        }
    };

    float acc[4][8][4];
#pragma unroll
    for (int mb = 0; mb < 4; mb++)
#pragma unroll
        for (int nb = 0; nb < 8; nb++)
#pragma unroll
            for (int j = 0; j < 4; j++) acc[mb][nb][j] = 0.f;

    const int part = lane >> 3, l7 = lane & 7;
    const int arow = wm * 64 + (part & 1) * 8 + l7;   // + mb*16
    const int acol = (part >> 1) * 8;                 // + k0
    const int brow = wn * 64 + (part >> 1) * 8 + l7;  // + nbp*16
    const int bcol = (part & 1) * 8;                  // + k0

    auto compute = [&](int buf) {
        const uint32_t da = sa_base + buf * (ABUF * 2);
        const uint32_t db = sb_base + buf * (BBUF * 2);
#pragma unroll
        for (int ks = 0; ks < 2; ks++) {
            const int k0 = ks * 16;
            uint32_t af[4][4];
#pragma unroll
            for (int mb = 0; mb < 4; mb++)
                ldmx4(af[mb], da + ((arow + mb * 16) * SSTR + k0 + acol) * 2);
#pragma unroll
            for (int nbp = 0; nbp < 4; nbp++) {
                uint32_t bf[4];
                ldmx4(bf, db + ((brow + nbp * 16) * SSTR + k0 + bcol) * 2);
#pragma unroll
                for (int mb = 0; mb < 4; mb++) {
                    mma16816(acc[mb][2 * nbp],     af[mb][0], af[mb][1], af[mb][2],
                             af[mb][3], bf[0], bf[1]);
                    mma16816(acc[mb][2 * nbp + 1], af[mb][0], af[mb][1], af[mb][2],
                             af[mb][3], bf[2], bf[3]);
                }
            }
        }
    };

    // 3-stage pipeline, one barrier per chunk.
    stage(0, 0); CP_COMMIT();
    stage(1, 1); CP_COMMIT();
#pragma unroll 1
    for (int kc = 0; kc < NCHUNK; kc++) {
        if (kc < NCHUNK - 1) { CP_WAIT(1); } else { CP_WAIT(0); }
        __syncthreads();
        if (kc + 2 < NCHUNK) { stage(kc + 2, (kc + 2) % 3); CP_COMMIT(); }
        compute(kc % 3);
    }

    // Epilogue: bias + STG (float2 pairs, rows ag / ag+8)
    const int aq   = 2 * (lane & 3);
    const int ag   = lane >> 2;
    const int colb = r * CH + wn * 64 + aq;
#pragma unroll
    for (int nb = 0; nb < 8; nb++) {
        const float2 b2 = *(const float2*)(bias + colb + nb * 8);
#pragma unroll
        for (int mb = 0; mb < 4; mb++) {
            const int row0 = m0 + wm * 64 + mb * 16 + ag;
            float* p0 = out + (size_t)row0 * OUTCOLS + colb + nb * 8;
            float* p1 = p0 + (size_t)8 * OUTCOLS;
            *(float2*)p0 = make_float2(acc[mb][nb][0] + b2.x, acc[mb][nb][1] + b2.y);
            *(float2*)p1 = make_float2(acc[mb][nb][2] + b2.x, acc[mb][nb][3] + b2.y);
        }
    }
}

extern "C" void kernel_launch(void* const* d_in, const int* in_sizes, int n_in,
                              void* d_out, int out_size) {
    (void)in_sizes; (void)n_in; (void)out_size;
    const float* x    = (const float*)d_in[0];
    const float* v    = (const float*)d_in[1];
    const float* bias = (const float*)d_in[2];
    float* out        = (float*)d_out;

    init_cells_kernel<<<1, 32>>>();
    convert_x_kernel<<<(BATCH * XCOLS) / (256 * 8), 256>>>(x);
    convert_v_kernel<<<ROWS, CH>>>(v);
    dim3 grid(BATCH / BM, ROWS);
    ticrows_hmma<<<grid, THREADS>>>(bias, out);
}

// round 12
// speedup vs baseline: 1.0912x; 1.0912x over previous
#include <cuda_runtime.h>
#include <cuda_fp16.h>
#include <cstdint>
#include <cstddef>

// ---------------------------------------------------------------------------
// TicRows via mma.sync m16n8k16 (fp16 in, fp32 acc).
// R8: 512 threads (16 warps, 32x64 warp tiles). B (v) tile fully resident in
// smem; all 3 A chunks (k=64 each == one board cell) cp.async'd up-front.
// Mainloop = 3x { wait_group; syncthreads; compute } -- no mid-loop staging.
// Pre-pass: x -> fp16 g_xh, v -> fp16 g_vT[r][n][k] (k-contiguous).
// out[n, r*256+c] = sum_{e,i} x[n, cell[r][e]*64+i]*v[e,i,r,c] + b[r*256+c]
// ---------------------------------------------------------------------------

#define BATCH   8192
#define ROWS    49
#define CH      256
#define XCOLS   1728
#define OUTCOLS 12544
#define KDIM    192
#define BM      128
#define BN      256
#define THREADS 512
#define ASTR    72            // A smem row stride (halves): 4n-bank map, cf ldmatrix
#define BSTR    200           // B smem row stride (halves): 100n -> 4n-bank map
#define ABUF    (BM * ASTR)   // per-chunk A buffer (halves)

// dynamic smem: 3 A chunks + resident B
#define SM_A(k)  ((k) * ABUF * 2)                 // bytes
#define SM_B     (3 * ABUF * 2)                   // 55296
#define SMEM_TOTAL (SM_B + BN * BSTR * 2)         // 55296 + 102400 = 157696

__device__ int    d_cell[ROWS * 3];
__device__ __half g_xh[(size_t)BATCH * XCOLS];
__device__ __half g_vT[(size_t)ROWS * CH * KDIM];

__global__ void init_cells_kernel() {
    if (threadIdx.x != 0) return;
    int step = 0, col = 0;
    auto put = [&](int x, int y, int z) {
        d_cell[col * 3 + step] = x + 3 * y + 9 * z;
        step = (step + 1) % 3;
    };
    for (int x = 0; x < 3; x++) {
        for (int y = 0; y < 3; y++) { for (int z = 0; z < 3; z++) put(x, y, z); col++; }
        for (int z = 0; z < 3; z++) { for (int y = 0; y < 3; y++) put(x, y, z); col++; }
        for (int y = 0; y < 3; y++) put(x, y, y);       col++;
        for (int y = 0; y < 3; y++) put(x, y, 2 - y);   col++;
    }
    for (int z = 0; z < 3; z++) {
        for (int y = 0; y < 3; y++) { for (int x = 0; x < 3; x++) put(x, y, z); col++; }
        for (int y = 0; y < 3; y++) put(y, y, z);       col++;
        for (int y = 0; y < 3; y++) put(2 - y, y, z);   col++;
    }
    for (int y = 0; y < 3; y++) {
        for (int z = 0; z < 3; z++) put(z, y, z);       col++;
        for (int z = 0; z < 3; z++) put(2 - z, y, z);   col++;
    }
    for (int x = 0; x < 3; x++) put(x, x, x);           col++;
    for (int x = 0; x < 3; x++) put(x, 2 - x, 2 - x);   col++;
    for (int x = 0; x < 3; x++) put(x, x, 2 - x);       col++;
    for (int x = 0; x < 3; x++) put(x, 2 - x, x);       col++;
}

__global__ void convert_x_kernel(const float* __restrict__ x) {
    const size_t i8 = ((size_t)blockIdx.x * blockDim.x + threadIdx.x) * 8;
    float4 a = *(const float4*)(x + i8);
    float4 b = *(const float4*)(x + i8 + 4);
    __half2 h[4] = { __floats2half2_rn(a.x, a.y), __floats2half2_rn(a.z, a.w),
                     __floats2half2_rn(b.x, b.y), __floats2half2_rn(b.z, b.w) };
    *(uint4*)(g_xh + i8) = *(uint4*)h;
}

__global__ void convert_v_kernel(const float* __restrict__ v) {
    const int r = blockIdx.x, n = threadIdx.x;
    const float* src = v + (size_t)r * CH + n;
    __half* dst = g_vT + ((size_t)r * CH + n) * KDIM;
#pragma unroll 1
    for (int kg = 0; kg < KDIM / 8; kg++) {
        __half2 h[4];
#pragma unroll
        for (int j = 0; j < 4; j++) {
            float f0 = src[(size_t)(kg * 8 + 2 * j)     * OUTCOLS];
            float f1 = src[(size_t)(kg * 8 + 2 * j + 1) * OUTCOLS];
            h[j] = __floats2half2_rn(f0, f1);
        }
        *(uint4*)(dst + kg * 8) = *(uint4*)h;
    }
}

// ------------------------------ PTX helpers -------------------------------

__device__ __forceinline__ uint32_t smem_u32(const void* p) {
    uint32_t a;
    asm("{ .reg .u64 t; cvta.to.shared.u64 t, %1; cvt.u32.u64 %0, t; }"
        : "=r"(a) : "l"(p));
    return a;
}
__device__ __forceinline__ void cp16(uint32_t dst, const void* src) {
    asm volatile("cp.async.ca.shared.global [%0], [%1], 16;"
                 :: "r"(dst), "l"(src) : "memory");
}
#define CP_COMMIT()  asm volatile("cp.async.commit_group;" ::: "memory")
#define CP_WAIT(n)   asm volatile("cp.async.wait_group %0;" :: "n"(n) : "memory")

__device__ __forceinline__ void ldmx4(uint32_t* r, uint32_t addr) {
    asm volatile("ldmatrix.sync.aligned.m8n8.x4.shared.b16 {%0,%1,%2,%3}, [%4];"
                 : "=r"(r[0]), "=r"(r[1]), "=r"(r[2]), "=r"(r[3]) : "r"(addr));
}
__device__ __forceinline__ void mma16816(float* c, uint32_t a0, uint32_t a1,
                                         uint32_t a2, uint32_t a3,
                                         uint32_t b0, uint32_t b1) {
    asm volatile(
        "mma.sync.aligned.m16n8k16.row.col.f32.f16.f16.f32 "
        "{%0,%1,%2,%3}, {%4,%5,%6,%7}, {%8,%9}, {%0,%1,%2,%3};"
        : "+f"(c[0]), "+f"(c[1]), "+f"(c[2]), "+f"(c[3])
        : "r"(a0), "r"(a1), "r"(a2), "r"(a3), "r"(b0), "r"(b1));
}

// ------------------------------- main kernel ------------------------------

__global__ __launch_bounds__(THREADS, 1)
void ticrows_hmma(const float* __restrict__ bias, float* __restrict__ out) {
    extern __shared__ char smem[];
    const uint32_t sbase = smem_u32(smem);

    const int tid  = threadIdx.x;
    const int lane = tid & 31;
    const int wid  = tid >> 5;
    const int wm   = wid >> 2;           // 4 warp-groups along M -> 32 rows each
    const int wn   = wid & 3;            // 4 along N -> 64 cols each
    const int m0   = blockIdx.x * BM;
    const int r    = blockIdx.y;

    const int ce0 = d_cell[r * 3 + 0];
    const int ce1 = d_cell[r * 3 + 1];
    const int ce2 = d_cell[r * 3 + 2];

    // ---- stage B (resident): 256 n-rows x 192 k halves = 6144 cp16 ----
    {
        const __half* vb = g_vT + (size_t)r * CH * KDIM;
#pragma unroll
        for (int i = 0; i < 12; i++) {
            const int c = tid + i * THREADS;        // 0..6143
            const int row = c / 24, seg = c % 24;
            cp16(sbase + SM_B + (row * BSTR + seg * 8) * 2,
                 vb + (size_t)row * KDIM + seg * 8);
        }
        CP_COMMIT();
    }
    // ---- stage all 3 A chunks: chunk kc = cell ce_kc's 64-col slab ----
    {
        const int cells[3] = { ce0, ce1, ce2 };
#pragma unroll
        for (int kc = 0; kc < 3; kc++) {
            const __half* xb = g_xh + (size_t)m0 * XCOLS + cells[kc] * 64;
#pragma unroll
            for (int i = 0; i < 2; i++) {
                const int c = tid + i * THREADS;    // 0..1023
                const int row = c >> 3, seg = c & 7;
                cp16(sbase + SM_A(kc) + (row * ASTR + seg * 8) * 2,
                     xb + (size_t)row * XCOLS + seg * 8);
            }
            CP_COMMIT();
        }
    }

    float acc[2][8][4];
#pragma unroll
    for (int mb = 0; mb < 2; mb++)
#pragma unroll
        for (int nb = 0; nb < 8; nb++)
#pragma unroll
            for (int j = 0; j < 4; j++) acc[mb][nb][j] = 0.f;

    const int part = lane >> 3, l7 = lane & 7;
    const int arow = wm * 32 + (part & 1) * 8 + l7;   // + mb*16
    const int acol = (part >> 1) * 8;                 // + k0
    const int brow = wn * 64 + (part >> 1) * 8 + l7;  // + nbp*16
    const int bcol = (part & 1) * 8;                  // + k0

    // ---- mainloop: 3 chunks, one wait+barrier each, no staging ----
#pragma unroll
    for (int kc = 0; kc < 3; kc++) {
        if (kc == 0)      CP_WAIT(2);
        else if (kc == 1) CP_WAIT(1);
        else              CP_WAIT(0);
        __syncthreads();

        const uint32_t da = sbase + SM_A(kc);
        const uint32_t db = sbase + SM_B;
#pragma unroll
        for (int ks = 0; ks < 4; ks++) {
            const int k0 = ks * 16;
            uint32_t af[2][4];
#pragma unroll
            for (int mb = 0; mb < 2; mb++)
                ldmx4(af[mb], da + ((arow + mb * 16) * ASTR + k0 + acol) * 2);
#pragma unroll
            for (int nbp = 0; nbp < 4; nbp++) {
                uint32_t bf[4];
                ldmx4(bf, db + ((brow + nbp * 16) * BSTR + kc * 64 + k0 + bcol) * 2);
#pragma unroll
                for (int mb = 0; mb < 2; mb++) {
                    mma16816(acc[mb][2 * nbp],     af[mb][0], af[mb][1], af[mb][2],
                             af[mb][3], bf[0], bf[1]);
                    mma16816(acc[mb][2 * nbp + 1], af[mb][0], af[mb][1], af[mb][2],
                             af[mb][3], bf[2], bf[3]);
                }
            }
        }
    }

    // ---- epilogue: bias + STG ----
    const int aq   = 2 * (lane & 3);
    const int ag   = lane >> 2;
    const int colb = r * CH + wn * 64 + aq;
#pragma unroll
    for (int nb = 0; nb < 8; nb++) {
        const float2 b2 = *(const float2*)(bias + colb + nb * 8);
#pragma unroll
        for (int mb = 0; mb < 2; mb++) {
            const int row0 = m0 + wm * 32 + mb * 16 + ag;
            float* p0 = out + (size_t)row0 * OUTCOLS + colb + nb * 8;
            float* p1 = p0 + (size_t)8 * OUTCOLS;
            *(float2*)p0 = make_float2(acc[mb][nb][0] + b2.x, acc[mb][nb][1] + b2.y);
            *(float2*)p1 = make_float2(acc[mb][nb][2] + b2.x, acc[mb][nb][3] + b2.y);
        }
    }
}

extern "C" void kernel_launch(void* const* d_in, const int* in_sizes, int n_in,
                              void* d_out, int out_size) {
    (void)in_sizes; (void)n_in; (void)out_size;
    const float* x    = (const float*)d_in[0];
    const float* v    = (const float*)d_in[1];
    const float* bias = (const float*)d_in[2];
    float* out        = (float*)d_out;

    cudaFuncSetAttribute(ticrows_hmma, cudaFuncAttributeMaxDynamicSharedMemorySize,
                         SMEM_TOTAL);

    init_cells_kernel<<<1, 32>>>();
    convert_x_kernel<<<(BATCH * XCOLS) / (256 * 8), 256>>>(x);
    convert_v_kernel<<<ROWS, CH>>>(v);
    dim3 grid(BATCH / BM, ROWS);
    ticrows_hmma<<<grid, THREADS, SMEM_TOTAL>>>(bias, out);
}

// round 16
// speedup vs baseline: 1.2023x; 1.1018x over previous
#include <cuda_runtime.h>
#include <cuda_fp16.h>
#include <cstdint>
#include <cstddef>

// ---------------------------------------------------------------------------
// TicRows via mma.sync m16n8k16 (fp16 in, fp32 acc).
// R13: persistent-style single wave. Grid = 3 x 49 = 147 CTAs; each CTA owns
// one r and ~21-22 m-tiles of 128 rows. B (v, 256x192) staged to smem ONCE per
// CTA; A double-buffered across tiles (cp.async overlaps compute+epilogue).
// One __syncthreads per tile. Pre-pass: x->fp16 g_xh, v->fp16 g_vT[r][n][k].
// out[n, r*256+c] = sum_{e,i} x[n, cell[r][e]*64+i]*v[e,i,r,c] + b[r*256+c]
// ---------------------------------------------------------------------------

#define BATCH   8192
#define ROWS    49
#define CH      256
#define XCOLS   1728
#define OUTCOLS 12544
#define KDIM    192
#define BM      128
#define THREADS 512
#define STR     200                 // smem row stride (halves); bank step 4 -> cf
#define ABUF    (BM * STR * 2)      // 51200 B per A buffer
#define SM_A(b) ((b) * ABUF)
#define SM_B    (2 * ABUF)          // 102400
#define SMEM_TOTAL (SM_B + CH * STR * 2)   // 204800

__device__ int    d_cell[ROWS * 3];
__device__ __half g_xh[(size_t)BATCH * XCOLS];
__device__ __half g_vT[(size_t)ROWS * CH * KDIM];

__global__ void init_cells_kernel() {
    if (threadIdx.x != 0) return;
    int step = 0, col = 0;
    auto put = [&](int x, int y, int z) {
        d_cell[col * 3 + step] = x + 3 * y + 9 * z;
        step = (step + 1) % 3;
    };
    for (int x = 0; x < 3; x++) {
        for (int y = 0; y < 3; y++) { for (int z = 0; z < 3; z++) put(x, y, z); col++; }
        for (int z = 0; z < 3; z++) { for (int y = 0; y < 3; y++) put(x, y, z); col++; }
        for (int y = 0; y < 3; y++) put(x, y, y);       col++;
        for (int y = 0; y < 3; y++) put(x, y, 2 - y);   col++;
    }
    for (int z = 0; z < 3; z++) {
        for (int y = 0; y < 3; y++) { for (int x = 0; x < 3; x++) put(x, y, z); col++; }
        for (int y = 0; y < 3; y++) put(y, y, z);       col++;
        for (int y = 0; y < 3; y++) put(2 - y, y, z);   col++;
    }
    for (int y = 0; y < 3; y++) {
        for (int z = 0; z < 3; z++) put(z, y, z);       col++;
        for (int z = 0; z < 3; z++) put(2 - z, y, z);   col++;
    }
    for (int x = 0; x < 3; x++) put(x, x, x);           col++;
    for (int x = 0; x < 3; x++) put(x, 2 - x, 2 - x);   col++;
    for (int x = 0; x < 3; x++) put(x, x, 2 - x);       col++;
    for (int x = 0; x < 3; x++) put(x, 2 - x, x);       col++;
}

__global__ void convert_x_kernel(const float* __restrict__ x) {
    const size_t i8 = ((size_t)blockIdx.x * blockDim.x + threadIdx.x) * 8;
    float4 a = *(const float4*)(x + i8);
    float4 b = *(const float4*)(x + i8 + 4);
    __half2 h[4] = { __floats2half2_rn(a.x, a.y), __floats2half2_rn(a.z, a.w),
                     __floats2half2_rn(b.x, b.y), __floats2half2_rn(b.z, b.w) };
    *(uint4*)(g_xh + i8) = *(uint4*)h;
}

__global__ void convert_v_kernel(const float* __restrict__ v) {
    const int r = blockIdx.x, n = threadIdx.x;
    const float* src = v + (size_t)r * CH + n;
    __half* dst = g_vT + ((size_t)r * CH + n) * KDIM;
#pragma unroll 1
    for (int kg = 0; kg < KDIM / 8; kg++) {
        __half2 h[4];
#pragma unroll
        for (int j = 0; j < 4; j++) {
            float f0 = src[(size_t)(kg * 8 + 2 * j)     * OUTCOLS];
            float f1 = src[(size_t)(kg * 8 + 2 * j + 1) * OUTCOLS];
            h[j] = __floats2half2_rn(f0, f1);
        }
        *(uint4*)(dst + kg * 8) = *(uint4*)h;
    }
}

// ------------------------------ PTX helpers -------------------------------

__device__ __forceinline__ uint32_t smem_u32(const void* p) {
    uint32_t a;
    asm("{ .reg .u64 t; cvta.to.shared.u64 t, %1; cvt.u32.u64 %0, t; }"
        : "=r"(a) : "l"(p));
    return a;
}
__device__ __forceinline__ void cp16(uint32_t dst, const void* src) {
    asm volatile("cp.async.ca.shared.global [%0], [%1], 16;"
                 :: "r"(dst), "l"(src) : "memory");
}
#define CP_COMMIT()  asm volatile("cp.async.commit_group;" ::: "memory")
#define CP_WAIT(n)   asm volatile("cp.async.wait_group %0;" :: "n"(n) : "memory")

__device__ __forceinline__ void ldmx4(uint32_t* r, uint32_t addr) {
    asm volatile("ldmatrix.sync.aligned.m8n8.x4.shared.b16 {%0,%1,%2,%3}, [%4];"
                 : "=r"(r[0]), "=r"(r[1]), "=r"(r[2]), "=r"(r[3]) : "r"(addr));
}
__device__ __forceinline__ void mma16816(float* c, uint32_t a0, uint32_t a1,
                                         uint32_t a2, uint32_t a3,
                                         uint32_t b0, uint32_t b1) {
    asm volatile(
        "mma.sync.aligned.m16n8k16.row.col.f32.f16.f16.f32 "
        "{%0,%1,%2,%3}, {%4,%5,%6,%7}, {%8,%9}, {%0,%1,%2,%3};"
        : "+f"(c[0]), "+f"(c[1]), "+f"(c[2]), "+f"(c[3])
        : "r"(a0), "r"(a1), "r"(a2), "r"(a3), "r"(b0), "r"(b1));
}

// ------------------------------- main kernel ------------------------------

__global__ __launch_bounds__(THREADS, 1)
void ticrows_hmma(const float* __restrict__ bias, float* __restrict__ out) {
    extern __shared__ char smem[];
    const uint32_t sbase = smem_u32(smem);

    const int tid  = threadIdx.x;
    const int lane = tid & 31;
    const int wid  = tid >> 5;
    const int wm   = wid >> 2;           // 4 along M -> 32 rows each
    const int wn   = wid & 3;            // 4 along N -> 64 cols each
    const int s    = blockIdx.x;         // slice within r: 0..2
    const int r    = blockIdx.y;

    // tile range: 64 m-tiles split 22/21/21
    const int cnt    = 21 + (s == 0);
    const int tstart = (s == 0) ? 0 : (22 + (s - 1) * 21);

    // ---- stage B once: 256 rows x 192 halves, stride STR ----
    {
        const __half* vb = g_vT + (size_t)r * CH * KDIM;
#pragma unroll
        for (int i = 0; i < 12; i++) {
            const int c = tid + i * THREADS;       // 0..6143
            const int row = c / 24, seg = c % 24;
            cp16(sbase + SM_B + (row * STR + seg * 8) * 2,
                 vb + (size_t)row * KDIM + seg * 8);
        }
        CP_COMMIT();
    }

    // ---- A staging precompute (constant per CTA): 3072 chunks, 6/thread ----
    int      a_src[6];        // element offset within a tile: row*XCOLS + col
    uint32_t a_dst[6];        // byte offset within an A buffer
    {
        const int ce[3] = { d_cell[r * 3], d_cell[r * 3 + 1], d_cell[r * 3 + 2] };
#pragma unroll
        for (int i = 0; i < 6; i++) {
            const int c = tid + i * THREADS;       // 0..3071
            const int row = c / 24, seg = c % 24;
            const int e = seg >> 3, w8 = (seg & 7) * 8;
            a_src[i] = row * XCOLS + ce[e] * 64 + w8;
            a_dst[i] = (row * STR + seg * 8) * 2;
        }
    }
    auto stageA = [&](int m0, int buf) {
        const __half* xb = g_xh + (size_t)m0 * XCOLS;
        const uint32_t da = sbase + SM_A(buf);
#pragma unroll
        for (int i = 0; i < 6; i++)
            cp16(da + a_dst[i], xb + a_src[i]);
    };

    // ---- fragment addressing ----
    const int part = lane >> 3, l7 = lane & 7;
    const int arow = wm * 32 + (part & 1) * 8 + l7;   // + mb*16
    const int acol = (part >> 1) * 8;                 // + k0
    const int brow = wn * 64 + (part >> 1) * 8 + l7;  // + nbp*16
    const int bcol = (part & 1) * 8;                  // + k0

    // ---- bias preload (constant per CTA) ----
    const int aq   = 2 * (lane & 3);
    const int ag   = lane >> 2;
    const int colb = r * CH + wn * 64 + aq;
    float2 b2[8];
#pragma unroll
    for (int nb = 0; nb < 8; nb++)
        b2[nb] = *(const float2*)(bias + colb + nb * 8);

    // ---- prologue: first A tile ----
    int m0 = tstart * BM;
    stageA(m0, 0);
    CP_COMMIT();

#pragma unroll 1
    for (int t = 0; t < cnt; t++) {
        CP_WAIT(0);
        __syncthreads();
        if (t + 1 < cnt) { stageA(m0 + BM, (t + 1) & 1); CP_COMMIT(); }

        float acc[2][8][4];
#pragma unroll
        for (int mb = 0; mb < 2; mb++)
#pragma unroll
            for (int nb = 0; nb < 8; nb++)
#pragma unroll
                for (int j = 0; j < 4; j++) acc[mb][nb][j] = 0.f;

        const uint32_t da = sbase + SM_A(t & 1);
        const uint32_t db = sbase + SM_B;
#pragma unroll
        for (int ks = 0; ks < 12; ks++) {
            const int k0 = ks * 16;
            uint32_t af[2][4];
#pragma unroll
            for (int mb = 0; mb < 2; mb++)
                ldmx4(af[mb], da + ((arow + mb * 16) * STR + k0 + acol) * 2);
#pragma unroll
            for (int nbp = 0; nbp < 4; nbp++) {
                uint32_t bf[4];
                ldmx4(bf, db + ((brow + nbp * 16) * STR + k0 + bcol) * 2);
#pragma unroll
                for (int mb = 0; mb < 2; mb++) {
                    mma16816(acc[mb][2 * nbp],     af[mb][0], af[mb][1], af[mb][2],
                             af[mb][3], bf[0], bf[1]);
                    mma16816(acc[mb][2 * nbp + 1], af[mb][0], af[mb][1], af[mb][2],
                             af[mb][3], bf[2], bf[3]);
                }
            }
        }

        // epilogue for tile t (overlaps with in-flight A(t+1) cp.async)
#pragma unroll
        for (int nb = 0; nb < 8; nb++) {
#pragma unroll
            for (int mb = 0; mb < 2; mb++) {
                const int row0 = m0 + wm * 32 + mb * 16 + ag;
                float* p0 = out + (size_t)row0 * OUTCOLS + colb + nb * 8;
                float* p1 = p0 + (size_t)8 * OUTCOLS;
                *(float2*)p0 = make_float2(acc[mb][nb][0] + b2[nb].x,
                                           acc[mb][nb][1] + b2[nb].y);
                *(float2*)p1 = make_float2(acc[mb][nb][2] + b2[nb].x,
                                           acc[mb][nb][3] + b2[nb].y);
            }
        }
        m0 += BM;
    }
}

extern "C" void kernel_launch(void* const* d_in, const int* in_sizes, int n_in,
                              void* d_out, int out_size) {
    (void)in_sizes; (void)n_in; (void)out_size;
    const float* x    = (const float*)d_in[0];
    const float* v    = (const float*)d_in[1];
    const float* bias = (const float*)d_in[2];
    float* out        = (float*)d_out;

    cudaFuncSetAttribute(ticrows_hmma, cudaFuncAttributeMaxDynamicSharedMemorySize,
                         SMEM_TOTAL);

    init_cells_kernel<<<1, 32>>>();
    convert_x_kernel<<<(BATCH * XCOLS) / (256 * 8), 256>>>(x);
    convert_v_kernel<<<ROWS, CH>>>(v);
    dim3 grid(3, ROWS);
    ticrows_hmma<<<grid, THREADS, SMEM_TOTAL>>>(bias, out);
}

// round 17
// speedup vs baseline: 1.2119x; 1.0079x over previous
#include <cuda_runtime.h>
#include <cuda_fp16.h>
#include <cstdint>
#include <cstddef>

// ---------------------------------------------------------------------------
// TicRows via mma.sync m16n8k16 (fp16 in, fp32 acc).
// R17: persistent single wave (147 CTAs = 3 slices x 49 r). 256 threads,
// 8 warps in 2(M) x 4(N), 64x64 warp tiles -> smem read duplication drops 33%
// vs 16-warp 32x64. B (v, 256x192) resident in smem per CTA; A double-buffered
// across m-tiles; one __syncthreads per tile.
// Pre-pass: x->fp16 g_xh, v->fp16 g_vT[r][n][k] (k-contiguous).
// out[n, r*256+c] = sum_{e,i} x[n, cell[r][e]*64+i]*v[e,i,r,c] + b[r*256+c]
// ---------------------------------------------------------------------------

#define BATCH   8192
#define ROWS    49
#define CH      256
#define XCOLS   1728
#define OUTCOLS 12544
#define KDIM    192
#define BM      128
#define THREADS 256
#define STR     200                 // smem row stride (halves); bank step 4 -> cf
#define ABUF    (BM * STR * 2)      // 51200 B per A buffer
#define SM_A(b) ((b) * ABUF)
#define SM_B    (2 * ABUF)          // 102400
#define SMEM_TOTAL (SM_B + CH * STR * 2)   // 204800

__device__ int    d_cell[ROWS * 3];
__device__ __half g_xh[(size_t)BATCH * XCOLS];
__device__ __half g_vT[(size_t)ROWS * CH * KDIM];

__global__ void init_cells_kernel() {
    if (threadIdx.x != 0) return;
    int step = 0, col = 0;
    auto put = [&](int x, int y, int z) {
        d_cell[col * 3 + step] = x + 3 * y + 9 * z;
        step = (step + 1) % 3;
    };
    for (int x = 0; x < 3; x++) {
        for (int y = 0; y < 3; y++) { for (int z = 0; z < 3; z++) put(x, y, z); col++; }
        for (int z = 0; z < 3; z++) { for (int y = 0; y < 3; y++) put(x, y, z); col++; }
        for (int y = 0; y < 3; y++) put(x, y, y);       col++;
        for (int y = 0; y < 3; y++) put(x, y, 2 - y);   col++;
    }
    for (int z = 0; z < 3; z++) {
        for (int y = 0; y < 3; y++) { for (int x = 0; x < 3; x++) put(x, y, z); col++; }
        for (int y = 0; y < 3; y++) put(y, y, z);       col++;
        for (int y = 0; y < 3; y++) put(2 - y, y, z);   col++;
    }
    for (int y = 0; y < 3; y++) {
        for (int z = 0; z < 3; z++) put(z, y, z);       col++;
        for (int z = 0; z < 3; z++) put(2 - z, y, z);   col++;
    }
    for (int x = 0; x < 3; x++) put(x, x, x);           col++;
    for (int x = 0; x < 3; x++) put(x, 2 - x, 2 - x);   col++;
    for (int x = 0; x < 3; x++) put(x, x, 2 - x);       col++;
    for (int x = 0; x < 3; x++) put(x, 2 - x, x);       col++;
}

__global__ void convert_x_kernel(const float* __restrict__ x) {
    const size_t i8 = ((size_t)blockIdx.x * blockDim.x + threadIdx.x) * 8;
    float4 a = *(const float4*)(x + i8);
    float4 b = *(const float4*)(x + i8 + 4);
    __half2 h[4] = { __floats2half2_rn(a.x, a.y), __floats2half2_rn(a.z, a.w),
                     __floats2half2_rn(b.x, b.y), __floats2half2_rn(b.z, b.w) };
    *(uint4*)(g_xh + i8) = *(uint4*)h;
}

__global__ void convert_v_kernel(const float* __restrict__ v) {
    const int r = blockIdx.x, n = threadIdx.x;
    const float* src = v + (size_t)r * CH + n;
    __half* dst = g_vT + ((size_t)r * CH + n) * KDIM;
#pragma unroll 1
    for (int kg = 0; kg < KDIM / 8; kg++) {
        __half2 h[4];
#pragma unroll
        for (int j = 0; j < 4; j++) {
            float f0 = src[(size_t)(kg * 8 + 2 * j)     * OUTCOLS];
            float f1 = src[(size_t)(kg * 8 + 2 * j + 1) * OUTCOLS];
            h[j] = __floats2half2_rn(f0, f1);
        }
        *(uint4*)(dst + kg * 8) = *(uint4*)h;
    }
}

// ------------------------------ PTX helpers -------------------------------

__device__ __forceinline__ uint32_t smem_u32(const void* p) {
    uint32_t a;
    asm("{ .reg .u64 t; cvta.to.shared.u64 t, %1; cvt.u32.u64 %0, t; }"
        : "=r"(a) : "l"(p));
    return a;
}
__device__ __forceinline__ void cp16(uint32_t dst, const void* src) {
    asm volatile("cp.async.ca.shared.global [%0], [%1], 16;"
                 :: "r"(dst), "l"(src) : "memory");
}
#define CP_COMMIT()  asm volatile("cp.async.commit_group;" ::: "memory")
#define CP_WAIT(n)   asm volatile("cp.async.wait_group %0;" :: "n"(n) : "memory")

__device__ __forceinline__ void ldmx4(uint32_t* r, uint32_t addr) {
    asm volatile("ldmatrix.sync.aligned.m8n8.x4.shared.b16 {%0,%1,%2,%3}, [%4];"
                 : "=r"(r[0]), "=r"(r[1]), "=r"(r[2]), "=r"(r[3]) : "r"(addr));
}
__device__ __forceinline__ void mma16816(float* c, uint32_t a0, uint32_t a1,
                                         uint32_t a2, uint32_t a3,
                                         uint32_t b0, uint32_t b1) {
    asm volatile(
        "mma.sync.aligned.m16n8k16.row.col.f32.f16.f16.f32 "
        "{%0,%1,%2,%3}, {%4,%5,%6,%7}, {%8,%9}, {%0,%1,%2,%3};"
        : "+f"(c[0]), "+f"(c[1]), "+f"(c[2]), "+f"(c[3])
        : "r"(a0), "r"(a1), "r"(a2), "r"(a3), "r"(b0), "r"(b1));
}

// ------------------------------- main kernel ------------------------------

__global__ __launch_bounds__(THREADS, 1)
void ticrows_hmma(const float* __restrict__ bias, float* __restrict__ out) {
    extern __shared__ char smem[];
    const uint32_t sbase = smem_u32(smem);

    const int tid  = threadIdx.x;
    const int lane = tid & 31;
    const int wid  = tid >> 5;
    const int wm   = wid >> 2;           // 2 along M -> 64 rows each
    const int wn   = wid & 3;            // 4 along N -> 64 cols each
    const int s    = blockIdx.x;         // slice within r: 0..2
    const int r    = blockIdx.y;

    const int cnt    = 21 + (s == 0);
    const int tstart = (s == 0) ? 0 : (22 + (s - 1) * 21);

    const int ce0 = d_cell[r * 3 + 0];
    const int ce1 = d_cell[r * 3 + 1];
    const int ce2 = d_cell[r * 3 + 2];

    // ---- stage B once: 256 rows x 192 halves, stride STR ----
    {
        const __half* vb = g_vT + (size_t)r * CH * KDIM;
#pragma unroll
        for (int i = 0; i < 24; i++) {
            const int c = tid + i * THREADS;       // 0..6143
            const int row = c / 24, seg = c % 24;
            cp16(sbase + SM_B + (row * STR + seg * 8) * 2,
                 vb + (size_t)row * KDIM + seg * 8);
        }
        CP_COMMIT();
    }

    // ---- A staging (addresses recomputed inline to save registers) ----
    auto stageA = [&](int m0, int buf) {
        const __half* xb = g_xh + (size_t)m0 * XCOLS;
        const uint32_t da = sbase + SM_A(buf);
#pragma unroll
        for (int i = 0; i < 12; i++) {
            const int c = tid + i * THREADS;       // 0..3071
            const int row = c / 24, seg = c % 24;
            const int e = seg >> 3, w8 = (seg & 7) * 8;
            const int cell = (e == 0) ? ce0 : ((e == 1) ? ce1 : ce2);
            cp16(da + (row * STR + seg * 8) * 2,
                 xb + (size_t)row * XCOLS + cell * 64 + w8);
        }
    };

    // ---- fragment addressing ----
    const int part = lane >> 3, l7 = lane & 7;
    const int arow = wm * 64 + (part & 1) * 8 + l7;   // + mb*16
    const int acol = (part >> 1) * 8;                 // + k0
    const int brow = wn * 64 + (part >> 1) * 8 + l7;  // + nbp*16
    const int bcol = (part & 1) * 8;                  // + k0

    // ---- bias preload ----
    const int aq   = 2 * (lane & 3);
    const int ag   = lane >> 2;
    const int colb = r * CH + wn * 64 + aq;
    float2 b2[8];
#pragma unroll
    for (int nb = 0; nb < 8; nb++)
        b2[nb] = *(const float2*)(bias + colb + nb * 8);

    // ---- prologue ----
    int m0 = tstart * BM;
    stageA(m0, 0);
    CP_COMMIT();

#pragma unroll 1
    for (int t = 0; t < cnt; t++) {
        CP_WAIT(0);
        __syncthreads();
        if (t + 1 < cnt) { stageA(m0 + BM, (t + 1) & 1); CP_COMMIT(); }

        float acc[4][8][4];
#pragma unroll
        for (int mb = 0; mb < 4; mb++)
#pragma unroll
            for (int nb = 0; nb < 8; nb++)
#pragma unroll
                for (int j = 0; j < 4; j++) acc[mb][nb][j] = 0.f;

        const uint32_t da = sbase + SM_A(t & 1);
        const uint32_t db = sbase + SM_B;
#pragma unroll
        for (int ks = 0; ks < 12; ks++) {
            const int k0 = ks * 16;
            uint32_t af[4][4];
#pragma unroll
            for (int mb = 0; mb < 4; mb++)
                ldmx4(af[mb], da + ((arow + mb * 16) * STR + k0 + acol) * 2);
#pragma unroll
            for (int nbp = 0; nbp < 4; nbp++) {
                uint32_t bf[4];
                ldmx4(bf, db + ((brow + nbp * 16) * STR + k0 + bcol) * 2);
#pragma unroll
                for (int mb = 0; mb < 4; mb++) {
                    mma16816(acc[mb][2 * nbp],     af[mb][0], af[mb][1], af[mb][2],
                             af[mb][3], bf[0], bf[1]);
                    mma16816(acc[mb][2 * nbp + 1], af[mb][0], af[mb][1], af[mb][2],
                             af[mb][3], bf[2], bf[3]);
                }
            }
        }

        // epilogue for tile t (overlaps in-flight A(t+1) cp.async)
#pragma unroll
        for (int nb = 0; nb < 8; nb++) {
#pragma unroll
            for (int mb = 0; mb < 4; mb++) {
                const int row0 = m0 + wm * 64 + mb * 16 + ag;
                float* p0 = out + (size_t)row0 * OUTCOLS + colb + nb * 8;
                float* p1 = p0 + (size_t)8 * OUTCOLS;
                *(float2*)p0 = make_float2(acc[mb][nb][0] + b2[nb].x,
                                           acc[mb][nb][1] + b2[nb].y);
                *(float2*)p1 = make_float2(acc[mb][nb][2] + b2[nb].x,
                                           acc[mb][nb][3] + b2[nb].y);
            }
        }
        m0 += BM;
    }
}

extern "C" void kernel_launch(void* const* d_in, const int* in_sizes, int n_in,
                              void* d_out, int out_size) {
    (void)in_sizes; (void)n_in; (void)out_size;
    const float* x    = (const float*)d_in[0];
    const float* v    = (const float*)d_in[1];
    const float* bias = (const float*)d_in[2];
    float* out        = (float*)d_out;

    cudaFuncSetAttribute(ticrows_hmma, cudaFuncAttributeMaxDynamicSharedMemorySize,
                         SMEM_TOTAL);

    init_cells_kernel<<<1, 32>>>();
    convert_x_kernel<<<(BATCH * XCOLS) / (256 * 8), 256>>>(x);
    convert_v_kernel<<<ROWS, CH>>>(v);
    dim3 grid(3, ROWS);
    ticrows_hmma<<<grid, THREADS, SMEM_TOTAL>>>(bias, out);
}